// round 1
// baseline (speedup 1.0000x reference)
#include <cuda_runtime.h>
#include <cuda_bf16.h>

// Problem constants (fixed by the reference)
#define B 8
#define N 2048
#define M 8192
#define C 64
#define NSEG 2048

// Scratch: per (batch, segment) channel sums and counts.
// 8*2048*64 floats = 16 MB, 8*2048 floats = 64 KB.
__device__ float g_sums[B * NSEG * C];
__device__ float g_cnt[B * NSEG];

// ---------------------------------------------------------------------------
// Kernel 1: zero the scratch buffers (vectorized float4 stores)
// ---------------------------------------------------------------------------
__global__ void zero_kernel() {
    const int total4 = (B * NSEG * C) / 4;           // 1,048,576 float4
    int i = blockIdx.x * blockDim.x + threadIdx.x;
    float4 z = make_float4(0.f, 0.f, 0.f, 0.f);
    if (i < total4) {
        reinterpret_cast<float4*>(g_sums)[i] = z;
    }
    // counts: 16384 floats = 4096 float4; reuse the first threads
    if (i < (B * NSEG) / 4) {
        reinterpret_cast<float4*>(g_cnt)[i] = z;
    }
}

// ---------------------------------------------------------------------------
// Kernel 2: scatter-add source rows into (batch, segment) sums.
// One thread per (b, m, c) element. Consecutive threads cover consecutive c,
// so both the global load and the REDG target addresses are coalesced
// (32 lanes hit 32 consecutive floats in one/two 128B lines).
// ---------------------------------------------------------------------------
__global__ void scatter_kernel(const int* __restrict__ index_source,
                               const float* __restrict__ array_source) {
    int idx = blockIdx.x * blockDim.x + threadIdx.x;   // [0, B*M*C)
    if (idx >= B * M * C) return;
    int c  = idx & (C - 1);
    int bm = idx >> 6;            // b*M + m
    int b  = bm >> 13;            // M = 8192 = 2^13
    int seg = index_source[bm];   // [B, M, 1] -> flat b*M+m
    float v = array_source[idx];
    atomicAdd(&g_sums[(b * NSEG + seg) * C + c], v);
    if (c == 0) {
        atomicAdd(&g_cnt[b * NSEG + seg], 1.0f);
    }
}

// ---------------------------------------------------------------------------
// Kernel 3: gather per target: out[b,n,:] = sums[b,it,:] / (1e-10 + cnt)
// One thread per (b, n, c). Sums are hot in L2 (16 MB).
// ---------------------------------------------------------------------------
__global__ void gather_kernel(const int* __restrict__ index_target,
                              float* __restrict__ out) {
    int idx = blockIdx.x * blockDim.x + threadIdx.x;   // [0, B*N*C)
    if (idx >= B * N * C) return;
    int c  = idx & (C - 1);
    int bn = idx >> 6;            // b*N + n
    int b  = bn >> 11;            // N = 2048 = 2^11
    int seg = index_target[bn];
    float cnt = g_cnt[b * NSEG + seg];
    float inv = 1.0f / (1e-10f + cnt);
    out[idx] = g_sums[(b * NSEG + seg) * C + c] * inv;
}

// ---------------------------------------------------------------------------
extern "C" void kernel_launch(void* const* d_in, const int* in_sizes, int n_in,
                              void* d_out, int out_size) {
    const int*   index_target = (const int*)d_in[0];   // [B, N, 1]
    const int*   index_source = (const int*)d_in[1];   // [B, M, 1]
    const float* array_source = (const float*)d_in[2]; // [B, M, C]
    float*       out          = (float*)d_out;         // [B, N, C]

    (void)in_sizes; (void)n_in; (void)out_size;

    {
        int total4 = (B * NSEG * C) / 4;
        int threads = 256;
        int blocks = (total4 + threads - 1) / threads;
        zero_kernel<<<blocks, threads>>>();
    }
    {
        int total = B * M * C;
        int threads = 256;
        int blocks = (total + threads - 1) / threads;
        scatter_kernel<<<blocks, threads>>>(index_source, array_source);
    }
    {
        int total = B * N * C;
        int threads = 256;
        int blocks = (total + threads - 1) / threads;
        gather_kernel<<<blocks, threads>>>(index_target, out);
    }
}

// round 2
// speedup vs baseline: 1.3785x; 1.3785x over previous
#include <cuda_runtime.h>
#include <cuda_bf16.h>

// Problem constants (fixed by the reference)
#define B 8
#define N 2048
#define M 8192
#define C 64
#define NSEG 2048

// Scratch: per (batch, segment) channel sums and counts.
// 8*2048*64 floats = 16 MB, 8*2048 floats = 64 KB.
__device__ float g_sums[B * NSEG * C];
__device__ float g_cnt[B * NSEG];

// ---------------------------------------------------------------------------
// Scatter: one thread per (b, m, c4) quad. 128-bit load + 128-bit vector
// reduction (red.global.add.v4.f32, sm_90+). Consecutive threads cover
// consecutive c4 so both LDG.128 and REDG.128 are fully coalesced.
// ---------------------------------------------------------------------------
__global__ void scatter_kernel(const int* __restrict__ index_source,
                               const float* __restrict__ array_source) {
    int t = blockIdx.x * blockDim.x + threadIdx.x;   // [0, B*M*16)
    if (t >= B * M * (C / 4)) return;
    int c4 = t & 15;              // which float4 within the row
    int bm = t >> 4;              // b*M + m
    int b  = bm >> 13;            // M = 8192 = 2^13
    int seg = __ldg(&index_source[bm]);
    float4 v = reinterpret_cast<const float4*>(array_source)[t];
    float* dst = &g_sums[(b * NSEG + seg) * C + c4 * 4];
    asm volatile("red.global.add.v4.f32 [%0], {%1, %2, %3, %4};"
                 :: "l"(dst), "f"(v.x), "f"(v.y), "f"(v.z), "f"(v.w)
                 : "memory");
    if (c4 == 0) {
        atomicAdd(&g_cnt[b * NSEG + seg], 1.0f);
    }
}

// ---------------------------------------------------------------------------
// Gather: one thread per (b, n, c4) quad. Sums are L2-resident (16 MB).
// The 16 lanes sharing one (b,n) hit the same cnt address -> L1 broadcast.
// ---------------------------------------------------------------------------
__global__ void gather_kernel(const int* __restrict__ index_target,
                              float* __restrict__ out) {
    int t = blockIdx.x * blockDim.x + threadIdx.x;   // [0, B*N*16)
    if (t >= B * N * (C / 4)) return;
    int c4 = t & 15;
    int bn = t >> 4;              // b*N + n
    int b  = bn >> 11;            // N = 2048 = 2^11
    int seg = __ldg(&index_target[bn]);
    float cnt = g_cnt[b * NSEG + seg];
    float inv = 1.0f / (1e-10f + cnt);
    float4 v = reinterpret_cast<const float4*>(g_sums)[(b * NSEG + seg) * 16 + c4];
    v.x *= inv; v.y *= inv; v.z *= inv; v.w *= inv;
    reinterpret_cast<float4*>(out)[t] = v;
}

// ---------------------------------------------------------------------------
extern "C" void kernel_launch(void* const* d_in, const int* in_sizes, int n_in,
                              void* d_out, int out_size) {
    const int*   index_target = (const int*)d_in[0];   // [B, N, 1]
    const int*   index_source = (const int*)d_in[1];   // [B, M, 1]
    const float* array_source = (const float*)d_in[2]; // [B, M, C]
    float*       out          = (float*)d_out;         // [B, N, C]

    (void)in_sizes; (void)n_in; (void)out_size;

    // Zero the scratch via memset nodes (HW-accelerated, no kernel ramp).
    void* sums_ptr = nullptr;
    void* cnt_ptr  = nullptr;
    cudaGetSymbolAddress(&sums_ptr, g_sums);
    cudaGetSymbolAddress(&cnt_ptr,  g_cnt);
    cudaMemsetAsync(sums_ptr, 0, (size_t)B * NSEG * C * sizeof(float), 0);
    cudaMemsetAsync(cnt_ptr,  0, (size_t)B * NSEG * sizeof(float), 0);

    {
        int total = B * M * (C / 4);          // 1,048,576
        int threads = 256;
        int blocks = (total + threads - 1) / threads;
        scatter_kernel<<<blocks, threads>>>(index_source, array_source);
    }
    {
        int total = B * N * (C / 4);          // 262,144
        int threads = 256;
        int blocks = (total + threads - 1) / threads;
        gather_kernel<<<blocks, threads>>>(index_target, out);
    }
}

// round 3
// speedup vs baseline: 1.4308x; 1.0379x over previous
#include <cuda_runtime.h>
#include <cuda_bf16.h>

// Problem constants (fixed by the reference)
#define B 8
#define N 2048
#define M 8192
#define C 64
#define NSEG 2048

#define UNROLL 4

// Scratch: per (batch, segment) channel sums and counts.
__device__ float g_sums[B * NSEG * C];   // 16 MB
__device__ float g_cnt[B * NSEG];        // 64 KB

// ---------------------------------------------------------------------------
// Scatter: UNROLL independent (load -> red.global.add.v4) chains per thread.
// Iteration k handles quad q = t + k*S; within an iteration the 16 lanes of a
// half-warp cover 16 consecutive float4s of one source row (coalesced LDG.128
// and consecutive REDG targets).
// ---------------------------------------------------------------------------
__global__ void scatter_kernel(const int* __restrict__ index_source,
                               const float* __restrict__ array_source) {
    const int S = (B * M * (C / 4)) / UNROLL;          // 262,144
    int t = blockIdx.x * blockDim.x + threadIdx.x;
    if (t >= S) return;

    int    q[UNROLL];
    int    seg[UNROLL];
    int    b[UNROLL];
    float4 v[UNROLL];

#pragma unroll
    for (int k = 0; k < UNROLL; k++) {
        q[k] = t + k * S;
        int bm = q[k] >> 4;
        b[k]   = bm >> 13;                  // M = 8192 = 2^13
        seg[k] = __ldg(&index_source[bm]);  // broadcast across 16 lanes
        v[k]   = reinterpret_cast<const float4*>(array_source)[q[k]];
    }
#pragma unroll
    for (int k = 0; k < UNROLL; k++) {
        int c4 = q[k] & 15;
        float* dst = &g_sums[(b[k] * NSEG + seg[k]) * C + c4 * 4];
        asm volatile("red.global.add.v4.f32 [%0], {%1, %2, %3, %4};"
                     :: "l"(dst), "f"(v[k].x), "f"(v[k].y), "f"(v[k].z), "f"(v[k].w)
                     : "memory");
        if (c4 == 0) {
            atomicAdd(&g_cnt[b[k] * NSEG + seg[k]], 1.0f);
        }
    }
}

// ---------------------------------------------------------------------------
// Gather: UNROLL independent (idx -> cnt/sums -> out) chains per thread.
// Sums are L2-resident; the chains overlap the ~234-cycle L2 latency.
// ---------------------------------------------------------------------------
__global__ void gather_kernel(const int* __restrict__ index_target,
                              float* __restrict__ out) {
    const int S = (B * N * (C / 4)) / UNROLL;          // 65,536
    int t = blockIdx.x * blockDim.x + threadIdx.x;
    if (t >= S) return;

    int    q[UNROLL];
    int    sidx[UNROLL];
    float  cnt[UNROLL];
    float4 v[UNROLL];

#pragma unroll
    for (int k = 0; k < UNROLL; k++) {
        q[k] = t + k * S;
        int bn = q[k] >> 4;
        int b  = bn >> 11;                  // N = 2048 = 2^11
        int seg = __ldg(&index_target[bn]);
        sidx[k] = b * NSEG + seg;
        cnt[k]  = g_cnt[sidx[k]];
        v[k]    = reinterpret_cast<const float4*>(g_sums)[sidx[k] * 16 + (q[k] & 15)];
    }
#pragma unroll
    for (int k = 0; k < UNROLL; k++) {
        float inv = 1.0f / (1e-10f + cnt[k]);
        float4 r = v[k];
        r.x *= inv; r.y *= inv; r.z *= inv; r.w *= inv;
        reinterpret_cast<float4*>(out)[q[k]] = r;
    }
}

// ---------------------------------------------------------------------------
extern "C" void kernel_launch(void* const* d_in, const int* in_sizes, int n_in,
                              void* d_out, int out_size) {
    const int*   index_target = (const int*)d_in[0];   // [B, N, 1]
    const int*   index_source = (const int*)d_in[1];   // [B, M, 1]
    const float* array_source = (const float*)d_in[2]; // [B, M, C]
    float*       out          = (float*)d_out;         // [B, N, C]

    (void)in_sizes; (void)n_in; (void)out_size;

    // Zero the scratch via memset nodes (HW-accelerated).
    void* sums_ptr = nullptr;
    void* cnt_ptr  = nullptr;
    cudaGetSymbolAddress(&sums_ptr, g_sums);
    cudaGetSymbolAddress(&cnt_ptr,  g_cnt);
    cudaMemsetAsync(sums_ptr, 0, (size_t)B * NSEG * C * sizeof(float), 0);
    cudaMemsetAsync(cnt_ptr,  0, (size_t)B * NSEG * sizeof(float), 0);

    {
        int total = (B * M * (C / 4)) / UNROLL;        // 262,144 threads
        int threads = 256;
        int blocks = (total + threads - 1) / threads;
        scatter_kernel<<<blocks, threads>>>(index_source, array_source);
    }
    {
        int total = (B * N * (C / 4)) / UNROLL;        // 65,536 threads
        int threads = 256;
        int blocks = (total + threads - 1) / threads;
        gather_kernel<<<blocks, threads>>>(index_target, out);
    }
}